// round 10
// baseline (speedup 1.0000x reference)
#include <cuda_runtime.h>
#include <cstdint>

#define EMBED_DIM   200
#define QUAD_DIM    50              // float4 chunks per row
#define ROW_BYTES   800
#define NUM_LAYERS  3
#define NUM_WALKS   25
#define BATCH       8192
#define ROWS        76              // rows gathered per (pair, side)
#define PAIRS_CTA   8
#define SLOTS       (PAIRS_CTA * 2) // 16
#define ENTRIES     (SLOTS * ROWS)  // 1216
#define NBUCKETS    16              // idx >> 16 -> ~36MB slice
#define NKEYS       (NBUCKETS * SLOTS) // 256
#define THREADS     256
#define GRID        (BATCH / PAIRS_CTA) // 1024 -> one resident wave

#define FMA4(A, W, V) do { \
    (A).x = fmaf((W), (V).x, (A).x); \
    (A).y = fmaf((W), (V).y, (A).y); \
    (A).z = fmaf((W), (V).z, (A).z); \
    (A).w = fmaf((W), (V).w, (A).w); } while (0)

// One sorted run with a fixed accumulator: branch-free hot loop.
#define RUN(ACC, KEY) do { \
    int _e = s_start[(KEY)]; \
    int _end = s_start[(KEY) + 1]; \
    _Pragma("unroll 4") \
    for (; _e < _end; _e++) { \
        unsigned _p = s_sorted[_e]; \
        float _w = s_wc[(_p >> 24) & 3u]; \
        float4 _v = __ldg(emb4 + (_p & 0xFFFFFu) * (unsigned)QUAD_DIM + j); \
        FMA4(ACC, _w, _v); \
    } } while (0)

__global__ __launch_bounds__(THREADS, 7)
void gnp_bucket_kernel(const float* __restrict__ emb,
                       const float* __restrict__ layer_w,
                       const int*   __restrict__ uidx,
                       const int*   __restrict__ iidx,
                       const int*   __restrict__ uwalks,
                       const int*   __restrict__ iwalks,
                       float*       __restrict__ out)
{
    __shared__ unsigned s_entries[ENTRIES];
    __shared__ unsigned s_sorted[ENTRIES];
    __shared__ int      s_cnt[NKEYS];
    __shared__ int      s_scan[NKEYS];
    __shared__ int      s_start[NKEYS + 1];
    __shared__ int      s_pos[NKEYS];
    __shared__ float    s_wc[4];
    __shared__ float    s_red[8][2];

    const int t = threadIdx.x;
    const int pair_base = blockIdx.x * PAIRS_CTA;

    if (t == 0) {
        float w0 = layer_w[0], w1 = layer_w[1], w2 = layer_w[2], w3 = layer_w[3];
        float m  = fmaxf(fmaxf(w0, w1), fmaxf(w2, w3));
        float e0 = __expf(w0 - m), e1 = __expf(w1 - m);
        float e2 = __expf(w2 - m), e3 = __expf(w3 - m);
        float inv = 1.0f / (e0 + e1 + e2 + e3);
        s_wc[0] = e0 * inv;
        s_wc[1] = e1 * inv * (1.0f / NUM_WALKS);
        s_wc[2] = e2 * inv * (1.0f / NUM_WALKS);
        s_wc[3] = e3 * inv * (1.0f / NUM_WALKS);
    }
    if (t < NKEYS) s_cnt[t] = 0;
    __syncthreads();

    // ---- stage packed entries + histogram over (bucket, slot) ----
    for (int e = t; e < ENTRIES; e += THREADS) {
        int s    = e / ROWS;            // slot 0..15
        int r    = e % ROWS;
        int side = s & 1;
        int b    = pair_base + (s >> 1);
        int idx, wc;
        if (r == 0) {
            idx = side ? iidx[b] : uidx[b];
            wc  = 0;
        } else {
            int w = (r - 1) / NUM_LAYERS;
            int l = (r - 1) % NUM_LAYERS;
            const int* walks = side ? iwalks : uwalks;
            idx = walks[(b * NUM_WALKS + w) * (NUM_LAYERS + 1) + l + 1];
            wc  = l + 1;
        }
        s_entries[e] = (unsigned)idx | ((unsigned)s << 20) | ((unsigned)wc << 24);
        atomicAdd(&s_cnt[((idx >> 16) << 4) | s], 1);
    }
    __syncthreads();

    // ---- exclusive scan over 256 keys (Hillis-Steele in SMEM) ----
    if (t < NKEYS) s_scan[t] = s_cnt[t];
    __syncthreads();
    #pragma unroll
    for (int off = 1; off < NKEYS; off <<= 1) {
        int add = 0;
        if (t < NKEYS && t >= off) add = s_scan[t - off];
        __syncthreads();
        if (t < NKEYS) s_scan[t] += add;
        __syncthreads();
    }
    if (t < NKEYS) {
        s_start[t + 1] = s_scan[t];
        int st = (t == 0) ? 0 : s_scan[t - 1];
        s_start[t] = st;
        s_pos[t]   = st;
    }
    __syncthreads();

    // ---- scatter into (bucket, slot)-sorted order ----
    for (int e = t; e < ENTRIES; e += THREADS) {
        unsigned p = s_entries[e];
        int key = ((int)((p & 0xFFFFFu) >> 16) << 4) | ((int)(p >> 20) & 15);
        s_sorted[atomicAdd(&s_pos[key], 1)] = p;
    }
    __syncthreads();

    // ---- phase-bucketed gather: quadrant q owns slots 4q..4q+3 ----
    const int q = t >> 6;
    const int j = t & 63;            // float4 chunk; j<50 active in runs
    float4 a0 = make_float4(0.f, 0.f, 0.f, 0.f);
    float4 a1 = a0, a2 = a0, a3 = a0;
    const float4* __restrict__ emb4 = (const float4*)emb;
    const char*   __restrict__ embc = (const char*)emb;

    #pragma unroll 1
    for (int k = 0; k < NBUCKETS; k++) {
        int kb = (k << 4) + (q << 2);

        if (j < QUAD_DIM) {
            RUN(a0, kb + 0);
            RUN(a1, kb + 1);
        }

        // ---- L2-prefetch bucket k+1's rows for this quadrant (all 64 lanes) ----
        if (k + 1 < NBUCKETS) {
            int pb   = kb + 16;                 // ((k+1)<<4) + (q<<2)
            int pbeg = s_start[pb];
            int pend = s_start[pb + 4];
            for (int i = pbeg + j; i < pend; i += 64) {
                unsigned row = s_sorted[i] & 0xFFFFFu;
                const char* p = embc + (size_t)row * ROW_BYTES;
                #pragma unroll
                for (int L = 0; L < 7; L++)
                    asm volatile("prefetch.global.L2 [%0];" :: "l"(p + L * 128));
            }
        }

        if (j < QUAD_DIM) {
            RUN(a2, kb + 2);
            RUN(a3, kb + 3);
        }
    }

    // slots 4q/4q+1 = pair 2q (user/item); 4q+2/4q+3 = pair 2q+1
    float p0 = a0.x * a1.x + a0.y * a1.y + a0.z * a1.z + a0.w * a1.w;
    float p1 = a2.x * a3.x + a2.y * a3.y + a2.z * a3.z + a2.w * a3.w;

    #pragma unroll
    for (int o = 16; o > 0; o >>= 1) {
        p0 += __shfl_down_sync(0xffffffffu, p0, o);
        p1 += __shfl_down_sync(0xffffffffu, p1, o);
    }
    const int warp = t >> 5;
    if ((t & 31) == 0) { s_red[warp][0] = p0; s_red[warp][1] = p1; }
    __syncthreads();

    if (t < 8) {
        int qq = t >> 1, pr = t & 1;
        out[pair_base + 2 * qq + pr] =
            s_red[2 * qq][pr] + s_red[2 * qq + 1][pr];
    }
}

extern "C" void kernel_launch(void* const* d_in, const int* in_sizes, int n_in,
                              void* d_out, int out_size)
{
    const float* emb     = (const float*)d_in[0];
    const float* weights = (const float*)d_in[1];
    const int*   uidx    = (const int*)  d_in[2];
    const int*   iidx    = (const int*)  d_in[3];
    const int*   uwalks  = (const int*)  d_in[4];
    const int*   iwalks  = (const int*)  d_in[5];
    float*       out     = (float*)d_out;

    gnp_bucket_kernel<<<GRID, THREADS>>>(emb, weights, uidx, iidx,
                                         uwalks, iwalks, out);
}

// round 11
// speedup vs baseline: 1.3926x; 1.3926x over previous
#include <cuda_runtime.h>
#include <cstdint>

#define EMBED_DIM   200
#define QUAD_DIM    50              // float4 chunks per row
#define ROW_BYTES   800
#define NUM_LAYERS  3
#define NUM_WALKS   25
#define BATCH       8192
#define ROWS        76              // rows gathered per (pair, side)
#define PAIRS_CTA   8
#define SLOTS       (PAIRS_CTA * 2) // 16
#define ENTRIES     (SLOTS * ROWS)  // 1216
#define NBUCKETS    16              // idx >> 16 -> ~36MB slice
#define NKEYS       (NBUCKETS * SLOTS) // 256
#define THREADS     256
#define GRID        (BATCH / PAIRS_CTA) // 1024 -> one resident wave

#define FMA4(A, W, V) do { \
    (A).x = fmaf((W), (V).x, (A).x); \
    (A).y = fmaf((W), (V).y, (A).y); \
    (A).z = fmaf((W), (V).z, (A).z); \
    (A).w = fmaf((W), (V).w, (A).w); } while (0)

// One sorted run with a fixed accumulator: branch-free hot loop.
#define RUN(ACC, KEY) do { \
    int _e = s_start[(KEY)]; \
    int _end = s_start[(KEY) + 1]; \
    _Pragma("unroll 4") \
    for (; _e < _end; _e++) { \
        unsigned _p = s_sorted[_e]; \
        float _w = s_wc[(_p >> 24) & 3u]; \
        float4 _v = __ldg(emb4 + (_p & 0xFFFFFu) * (unsigned)QUAD_DIM + j); \
        FMA4(ACC, _w, _v); \
    } } while (0)

__global__ __launch_bounds__(THREADS, 7)
void gnp_bucket_kernel(const float* __restrict__ emb,
                       const float* __restrict__ layer_w,
                       const int*   __restrict__ uidx,
                       const int*   __restrict__ iidx,
                       const int*   __restrict__ uwalks,
                       const int*   __restrict__ iwalks,
                       float*       __restrict__ out)
{
    __shared__ unsigned s_entries[ENTRIES];
    __shared__ unsigned s_sorted[ENTRIES];
    __shared__ int      s_cnt[NKEYS];
    __shared__ int      s_scan[NKEYS];
    __shared__ int      s_start[NKEYS + 1];
    __shared__ int      s_pos[NKEYS];
    __shared__ float    s_wc[4];
    __shared__ float    s_red[8][2];

    const int t = threadIdx.x;
    const int pair_base = blockIdx.x * PAIRS_CTA;

    if (t == 0) {
        float w0 = layer_w[0], w1 = layer_w[1], w2 = layer_w[2], w3 = layer_w[3];
        float m  = fmaxf(fmaxf(w0, w1), fmaxf(w2, w3));
        float e0 = __expf(w0 - m), e1 = __expf(w1 - m);
        float e2 = __expf(w2 - m), e3 = __expf(w3 - m);
        float inv = 1.0f / (e0 + e1 + e2 + e3);
        s_wc[0] = e0 * inv;
        s_wc[1] = e1 * inv * (1.0f / NUM_WALKS);
        s_wc[2] = e2 * inv * (1.0f / NUM_WALKS);
        s_wc[3] = e3 * inv * (1.0f / NUM_WALKS);
    }
    if (t < NKEYS) s_cnt[t] = 0;
    __syncthreads();

    // ---- stage packed entries + histogram over (bucket, slot) ----
    for (int e = t; e < ENTRIES; e += THREADS) {
        int s    = e / ROWS;            // slot 0..15
        int r    = e % ROWS;
        int side = s & 1;
        int b    = pair_base + (s >> 1);
        int idx, wc;
        if (r == 0) {
            idx = side ? iidx[b] : uidx[b];
            wc  = 0;
        } else {
            int w = (r - 1) / NUM_LAYERS;
            int l = (r - 1) % NUM_LAYERS;
            const int* walks = side ? iwalks : uwalks;
            idx = walks[(b * NUM_WALKS + w) * (NUM_LAYERS + 1) + l + 1];
            wc  = l + 1;
        }
        s_entries[e] = (unsigned)idx | ((unsigned)s << 20) | ((unsigned)wc << 24);
        atomicAdd(&s_cnt[((idx >> 16) << 4) | s], 1);
    }
    __syncthreads();

    // ---- exclusive scan over 256 keys (Hillis-Steele in SMEM) ----
    if (t < NKEYS) s_scan[t] = s_cnt[t];
    __syncthreads();
    #pragma unroll
    for (int off = 1; off < NKEYS; off <<= 1) {
        int add = 0;
        if (t < NKEYS && t >= off) add = s_scan[t - off];
        __syncthreads();
        if (t < NKEYS) s_scan[t] += add;
        __syncthreads();
    }
    if (t < NKEYS) {
        s_start[t + 1] = s_scan[t];
        int st = (t == 0) ? 0 : s_scan[t - 1];
        s_start[t] = st;
        s_pos[t]   = st;
    }
    __syncthreads();

    // ---- scatter into (bucket, slot)-sorted order ----
    for (int e = t; e < ENTRIES; e += THREADS) {
        unsigned p = s_entries[e];
        int key = ((int)((p & 0xFFFFFu) >> 16) << 4) | ((int)(p >> 20) & 15);
        s_sorted[atomicAdd(&s_pos[key], 1)] = p;
    }
    __syncthreads();

    // ---- phase-bucketed gather: quadrant q owns slots 4q..4q+3 ----
    const int q = t >> 6;
    const int j = t & 63;            // float4 chunk; j<50 active in runs
    float4 a0 = make_float4(0.f, 0.f, 0.f, 0.f);
    float4 a1 = a0, a2 = a0, a3 = a0;
    const float4* __restrict__ emb4 = (const float4*)emb;
    const char*   __restrict__ embc = (const char*)emb;
    const unsigned cls = (unsigned)blockIdx.x & 3u;

    #pragma unroll 1
    for (int k = 0; k < NBUCKETS; k++) {
        int kb = (k << 4) + (q << 2);

        if (j < QUAD_DIM) {
            RUN(a0, kb + 0);
            RUN(a1, kb + 1);
            RUN(a2, kb + 2);
            RUN(a3, kb + 3);
        }

        // ---- tail prefetch: ~40% of next bucket's rows, deduped by
        //      (row & 3) == (bid & 3), issued in the DRAM-idle phase tail ----
        if (k + 1 < NBUCKETS) {
            int pb   = kb + 16;                 // ((k+1)<<4) + (q<<2)
            int pbeg = s_start[pb];
            int pend = s_start[pb + 4];
            for (int i = pbeg + j; i < pend; i += 64) {
                unsigned row = s_sorted[i] & 0xFFFFFu;
                if ((row & 3u) == cls) {
                    const char* p = embc + (size_t)row * ROW_BYTES;
                    #pragma unroll
                    for (int L = 0; L < 7; L++)
                        asm volatile("prefetch.global.L2 [%0];" :: "l"(p + L * 128));
                }
            }
        }
    }

    // slots 4q/4q+1 = pair 2q (user/item); 4q+2/4q+3 = pair 2q+1
    float p0 = a0.x * a1.x + a0.y * a1.y + a0.z * a1.z + a0.w * a1.w;
    float p1 = a2.x * a3.x + a2.y * a3.y + a2.z * a3.z + a2.w * a3.w;

    #pragma unroll
    for (int o = 16; o > 0; o >>= 1) {
        p0 += __shfl_down_sync(0xffffffffu, p0, o);
        p1 += __shfl_down_sync(0xffffffffu, p1, o);
    }
    const int warp = t >> 5;
    if ((t & 31) == 0) { s_red[warp][0] = p0; s_red[warp][1] = p1; }
    __syncthreads();

    if (t < 8) {
        int qq = t >> 1, pr = t & 1;
        out[pair_base + 2 * qq + pr] =
            s_red[2 * qq][pr] + s_red[2 * qq + 1][pr];
    }
}

extern "C" void kernel_launch(void* const* d_in, const int* in_sizes, int n_in,
                              void* d_out, int out_size)
{
    const float* emb     = (const float*)d_in[0];
    const float* weights = (const float*)d_in[1];
    const int*   uidx    = (const int*)  d_in[2];
    const int*   iidx    = (const int*)  d_in[3];
    const int*   uwalks  = (const int*)  d_in[4];
    const int*   iwalks  = (const int*)  d_in[5];
    float*       out     = (float*)d_out;

    gnp_bucket_kernel<<<GRID, THREADS>>>(emb, weights, uidx, iidx,
                                         uwalks, iwalks, out);
}